// round 4
// baseline (speedup 1.0000x reference)
#include <cuda_runtime.h>
#include <math.h>

#define NNODES 100000
#define NEDGES 1600000
#define MAXF 256
#define SCAN_BS 256

// Scratch (device globals; allocation-free per harness rules)
__device__ float g_dis[NNODES];
__device__ float g_xw[(size_t)NNODES * MAXF];
__device__ float g_h0[(size_t)NNODES * MAXF];
__device__ float g_h1[(size_t)NNODES * MAXF];
__device__ int   g_rows[NEDGES];
__device__ int   g_cols[NEDGES];
__device__ int   g_cnt[NNODES];
__device__ int   g_cur[NNODES];
__device__ int   g_rowptr[NNODES + 1];
__device__ int   g_btot[(NNODES + SCAN_BS - 1) / SCAN_BS + 1];
__device__ int   g_boff[(NNODES + SCAN_BS - 1) / SCAN_BS + 1];
__device__ int   g_csr_src[NEDGES];
__device__ float g_csr_norm[NEDGES];
__device__ int   g_is64;

// ---------------------------------------------------------------------------
// Edge-index dtype detection
// ---------------------------------------------------------------------------
__global__ void detect_dtype_kernel(const void* ei_raw, int N) {
    const long long* p = (const long long*)ei_raw;
    int ok = 1;
    for (int i = 0; i < 8; i++) {
        long long v = p[i];
        if (v < 0 || v >= (long long)N) ok = 0;
    }
    g_is64 = ok;
}

__global__ void zero_kernel(int N) {
    int i = blockIdx.x * blockDim.x + threadIdx.x;
    if (i < N) { g_cnt[i] = 0; g_cur[i] = 0; }
}

__global__ void convert_count_kernel(const void* ei_raw, int E) {
    int e = blockIdx.x * blockDim.x + threadIdx.x;
    if (e >= E) return;
    int r, c;
    if (g_is64) {
        const long long* p = (const long long*)ei_raw;
        r = (int)p[e];
        c = (int)p[(size_t)E + e];
    } else {
        const int* p = (const int*)ei_raw;
        r = p[e];
        c = p[E + e];
    }
    g_rows[e] = r;
    g_cols[e] = c;
    atomicAdd(&g_cnt[c], 1);
}

// ---------------------------------------------------------------------------
// Exclusive scan of g_cnt -> g_rowptr
// ---------------------------------------------------------------------------
__global__ void scan_blocks_kernel(int N) {
    __shared__ int s[SCAN_BS];
    int i = blockIdx.x * SCAN_BS + threadIdx.x;
    int v = (i < N) ? g_cnt[i] : 0;
    s[threadIdx.x] = v;
    __syncthreads();
    for (int off = 1; off < SCAN_BS; off <<= 1) {
        int t = (threadIdx.x >= off) ? s[threadIdx.x - off] : 0;
        __syncthreads();
        s[threadIdx.x] += t;
        __syncthreads();
    }
    if (i < N) g_rowptr[i] = s[threadIdx.x] - v;
    if (threadIdx.x == SCAN_BS - 1) g_btot[blockIdx.x] = s[SCAN_BS - 1];
}

__global__ void scan_tops_kernel(int nblocks) {
    __shared__ int s[512];
    int v = (threadIdx.x < nblocks) ? g_btot[threadIdx.x] : 0;
    s[threadIdx.x] = v;
    __syncthreads();
    for (int off = 1; off < 512; off <<= 1) {
        int t = (threadIdx.x >= off) ? s[threadIdx.x - off] : 0;
        __syncthreads();
        s[threadIdx.x] += t;
        __syncthreads();
    }
    if (threadIdx.x < nblocks) g_boff[threadIdx.x] = s[threadIdx.x] - v;
}

__global__ void scan_add_kernel(int N, int E) {
    int i = blockIdx.x * SCAN_BS + threadIdx.x;
    if (i < N) g_rowptr[i] += g_boff[blockIdx.x];
    if (i == 0) g_rowptr[N] = E;
}

__global__ void finalize_dis_kernel(int N) {
    int i = blockIdx.x * blockDim.x + threadIdx.x;
    if (i < N) g_dis[i] = rsqrtf((float)g_cnt[i] + 1.0f);
}

__global__ void fill_csr_kernel(int E) {
    int e = blockIdx.x * blockDim.x + threadIdx.x;
    if (e >= E) return;
    int r = g_rows[e];
    int c = g_cols[e];
    int pos = g_rowptr[c] + atomicAdd(&g_cur[c], 1);
    g_csr_src[pos] = r;
    g_csr_norm[pos] = g_dis[r] * g_dis[c];
}

// ---------------------------------------------------------------------------
// Fused GEMM with packed f32x2 FMA:
//   xw = act(A) @ W ;  agg = xw * dis[row]^2 + bias   (self-loop init)
// 128x128 tile, BK=8, 256 threads, 8x8 per thread, accumulators as f32x2 pairs.
// ---------------------------------------------------------------------------
template <bool RELU_A>
__global__ __launch_bounds__(256)
void gemm_gcn_kernel(const float* __restrict__ A, const float* __restrict__ W,
                     const float* __restrict__ bias, const float* __restrict__ dis,
                     float* __restrict__ xw, float* __restrict__ agg,
                     int N, int K, int F)
{
    __shared__ float As[8][128];
    __shared__ float Bs[8][128];

    const int tid = threadIdx.x;
    const int bm = blockIdx.x, bn = blockIdx.y;
    const int tx = tid & 15, ty = tid >> 4;
    const int row0 = bm * 128 + ty * 8;
    const int col0 = bn * 128 + tx * 8;

    const int a_r = tid >> 1;           // 0..127
    const int a_k = (tid & 1) * 4;      // 0 or 4
    const int b_k = tid >> 5;           // 0..7
    const int b_c = (tid & 31) * 4;     // 0..124

    const int arow = bm * 128 + a_r;
    const bool avalid = (arow < N);
    const float* Arow = A + (size_t)arow * K;
    const float* Wbase = W + bn * 128 + b_c;

    float bj[8];
#pragma unroll
    for (int j = 0; j < 8; j++) bj[j] = bias[col0 + j];

    // acc2[i][jp] = packed pair (acc[i][2jp], acc[i][2jp+1])
    unsigned long long acc2[8][4];
#pragma unroll
    for (int i = 0; i < 8; i++)
#pragma unroll
        for (int jp = 0; jp < 4; jp++) acc2[i][jp] = 0ULL;

    // prefetch first tile into regs
    float4 av = make_float4(0.f, 0.f, 0.f, 0.f);
    if (avalid) av = *(const float4*)(Arow + a_k);
    float4 bv = *(const float4*)(Wbase + (size_t)b_k * F);

    for (int k0 = 0; k0 < K; k0 += 8) {
        if (RELU_A) {
            av.x = fmaxf(av.x, 0.f); av.y = fmaxf(av.y, 0.f);
            av.z = fmaxf(av.z, 0.f); av.w = fmaxf(av.w, 0.f);
        }
        As[a_k + 0][a_r] = av.x;
        As[a_k + 1][a_r] = av.y;
        As[a_k + 2][a_r] = av.z;
        As[a_k + 3][a_r] = av.w;
        *(float4*)&Bs[b_k][b_c] = bv;
        __syncthreads();

        // prefetch next tile while computing
        int kn = k0 + 8;
        if (kn < K) {
            if (avalid) av = *(const float4*)(Arow + kn + a_k);
            bv = *(const float4*)(Wbase + (size_t)(kn + b_k) * F);
        }

#pragma unroll
        for (int kk = 0; kk < 8; kk++) {
            // A scalars -> dup-packed u64
            float a[8];
            *(float4*)&a[0] = *(const float4*)&As[kk][ty * 8];
            *(float4*)&a[4] = *(const float4*)&As[kk][ty * 8 + 4];
            unsigned long long a2[8];
#pragma unroll
            for (int i = 0; i < 8; i++)
                asm("mov.b64 %0, {%1, %1};" : "=l"(a2[i]) : "f"(a[i]));

            // B pairs load directly as u64 (j-contiguous)
            unsigned long long b2[4];
            ulong2 lb0 = *(const ulong2*)&Bs[kk][tx * 8];
            ulong2 lb1 = *(const ulong2*)&Bs[kk][tx * 8 + 4];
            b2[0] = lb0.x; b2[1] = lb0.y; b2[2] = lb1.x; b2[3] = lb1.y;

#pragma unroll
            for (int i = 0; i < 8; i++)
#pragma unroll
                for (int jp = 0; jp < 4; jp++)
                    asm("fma.rn.f32x2 %0, %1, %2, %0;"
                        : "+l"(acc2[i][jp]) : "l"(a2[i]), "l"(b2[jp]));
        }
        __syncthreads();
    }

    // unpack accumulators
    float acc[8][8];
#pragma unroll
    for (int i = 0; i < 8; i++)
#pragma unroll
        for (int jp = 0; jp < 4; jp++)
            asm("mov.b64 {%0, %1}, %2;"
                : "=f"(acc[i][2 * jp]), "=f"(acc[i][2 * jp + 1]) : "l"(acc2[i][jp]));

#pragma unroll
    for (int i = 0; i < 8; i++) {
        int row = row0 + i;
        if (row < N) {
            float d = dis[row];
            float d2 = d * d;
            size_t base = (size_t)row * F + col0;
#pragma unroll
            for (int jq = 0; jq < 8; jq += 4) {
                float4 v = make_float4(acc[i][jq], acc[i][jq + 1], acc[i][jq + 2], acc[i][jq + 3]);
                *(float4*)(xw + base + jq) = v;
                float4 g = make_float4(v.x * d2 + bj[jq],
                                       v.y * d2 + bj[jq + 1],
                                       v.z * d2 + bj[jq + 2],
                                       v.w * d2 + bj[jq + 3]);
                *(float4*)(agg + base + jq) = g;
            }
        }
    }
}

// ---------------------------------------------------------------------------
// CSR gather-side aggregation (no atomics)
// ---------------------------------------------------------------------------
template <int F>
__global__ __launch_bounds__(256)
void csr_agg_kernel(const float* __restrict__ xw, float* __restrict__ agg, int N)
{
    const int lane = threadIdx.x & 31;
    const int node = (blockIdx.x * blockDim.x + threadIdx.x) >> 5;
    if (node >= N) return;

    int beg = g_rowptr[node];
    int end = g_rowptr[node + 1];
    if (beg == end) return;

    constexpr int NV = F / 128;
    float4 acc[NV];
#pragma unroll
    for (int q = 0; q < NV; q++) acc[q] = make_float4(0.f, 0.f, 0.f, 0.f);

    for (int base = beg; base < end; base += 32) {
        int n = min(32, end - base);
        int srcReg = 0; float nrReg = 0.f;
        if (lane < n) {
            srcReg = g_csr_src[base + lane];
            nrReg  = g_csr_norm[base + lane];
        }
        for (int k = 0; k < n; k++) {
            int   r = __shfl_sync(0xffffffffu, srcReg, k);
            float w = __shfl_sync(0xffffffffu, nrReg, k);
            const float4* s = (const float4*)(xw + (size_t)r * F);
#pragma unroll
            for (int q = 0; q < NV; q++) {
                float4 v = s[lane + q * 32];
                acc[q].x += w * v.x;
                acc[q].y += w * v.y;
                acc[q].z += w * v.z;
                acc[q].w += w * v.w;
            }
        }
    }

    float4* d = (float4*)(agg + (size_t)node * F);
#pragma unroll
    for (int q = 0; q < NV; q++) {
        float4 cur = d[lane + q * 32];
        cur.x += acc[q].x; cur.y += acc[q].y;
        cur.z += acc[q].z; cur.w += acc[q].w;
        d[lane + q * 32] = cur;
    }
}

// ---------------------------------------------------------------------------
// Heads
// ---------------------------------------------------------------------------
__global__ __launch_bounds__(256)
void head16_kernel(const float* __restrict__ A, const float* __restrict__ Wc,
                   const float* __restrict__ bc, float* __restrict__ out, int N)
{
    __shared__ float Ws[128 * 16];
    __shared__ float bs[16];
    for (int i = threadIdx.x; i < 128 * 16; i += 256) Ws[i] = Wc[i];
    if (threadIdx.x < 16) bs[threadIdx.x] = bc[threadIdx.x];
    __syncthreads();

    int j = threadIdx.x & 15;
    int rl = threadIdx.x >> 4;
    int row = blockIdx.x * 16 + rl;
    if (row >= N) return;

    const float* a = A + (size_t)row * 128;
    float acc = 0.f;
#pragma unroll 8
    for (int k = 0; k < 128; k++) acc += a[k] * Ws[k * 16 + j];
    out[(size_t)row * 16 + j] = acc + bs[j];
}

__global__ __launch_bounds__(256)
void head2_sigmoid_kernel(const float* __restrict__ A, const float* __restrict__ Wt,
                          const float* __restrict__ bt, float* __restrict__ out, int N)
{
    __shared__ float Ws[128 * 2];
    __shared__ float bs[2];
    for (int i = threadIdx.x; i < 128 * 2; i += 256) Ws[i] = Wt[i];
    if (threadIdx.x < 2) bs[threadIdx.x] = bt[threadIdx.x];
    __syncthreads();

    int j = threadIdx.x & 1;
    int rl = threadIdx.x >> 1;
    int row = blockIdx.x * 128 + rl;
    if (row >= N) return;

    const float* a = A + (size_t)row * 128;
    float acc = 0.f;
#pragma unroll 8
    for (int k = 0; k < 128; k++) acc += a[k] * Ws[k * 2 + j];
    float z = acc + bs[j];
    out[(size_t)row * 2 + j] = 1.0f / (1.0f + expf(-z));
}

// ---------------------------------------------------------------------------
// Launch
// ---------------------------------------------------------------------------
extern "C" void kernel_launch(void* const* d_in, const int* in_sizes, int n_in,
                              void* d_out, int out_size)
{
    const float* x = (const float*)d_in[0];
    const void* ei = d_in[1];
    const float* W1  = (const float*)d_in[2];
    const float* b1  = (const float*)d_in[3];
    const float* W2  = (const float*)d_in[4];
    const float* b2  = (const float*)d_in[5];
    const float* Wc  = (const float*)d_in[6];
    const float* bc  = (const float*)d_in[7];
    const float* We1 = (const float*)d_in[8];
    const float* be1 = (const float*)d_in[9];
    const float* We2 = (const float*)d_in[10];
    const float* be2 = (const float*)d_in[11];
    const float* We3 = (const float*)d_in[12];
    const float* be3 = (const float*)d_in[13];
    const float* We4 = (const float*)d_in[14];
    const float* be4 = (const float*)d_in[15];
    const float* Wt  = (const float*)d_in[16];
    const float* bt  = (const float*)d_in[17];
    float* out = (float*)d_out;

    const int N = in_sizes[0] / 128;
    const int E = in_sizes[1] / 2;
    const int nscan = (N + SCAN_BS - 1) / SCAN_BS;

    float *dis, *xw, *h0, *h1;
    cudaGetSymbolAddress((void**)&dis, g_dis);
    cudaGetSymbolAddress((void**)&xw, g_xw);
    cudaGetSymbolAddress((void**)&h0, g_h0);
    cudaGetSymbolAddress((void**)&h1, g_h1);

    // --- preprocessing: dtype, degrees, scan, CSR, norms ---
    detect_dtype_kernel<<<1, 1>>>(ei, N);
    zero_kernel<<<(N + 255) / 256, 256>>>(N);
    convert_count_kernel<<<(E + 255) / 256, 256>>>(ei, E);
    scan_blocks_kernel<<<nscan, SCAN_BS>>>(N);
    scan_tops_kernel<<<1, 512>>>(nscan);
    scan_add_kernel<<<nscan, SCAN_BS>>>(N, E);
    finalize_dis_kernel<<<(N + 255) / 256, 256>>>(N);
    fill_csr_kernel<<<(E + 255) / 256, 256>>>(E);

    dim3 gemm_grid_wide((N + 127) / 128, 2);   // F=256
    dim3 gemm_grid((N + 127) / 128, 1);        // F=128
    const int AGG_BLOCKS = (N + 7) / 8;

    // --- classification branch ---
    gemm_gcn_kernel<false><<<gemm_grid_wide, 256>>>(x, W1, b1, dis, xw, h0, N, 128, 256);
    csr_agg_kernel<256><<<AGG_BLOCKS, 256>>>(xw, h0, N);
    gemm_gcn_kernel<true><<<gemm_grid, 256>>>(h0, W2, b2, dis, xw, h1, N, 256, 128);
    csr_agg_kernel<128><<<AGG_BLOCKS, 256>>>(xw, h1, N);
    head16_kernel<<<(N + 15) / 16, 256>>>(h1, Wc, bc, out, N);

    // --- encoder branch ---
    gemm_gcn_kernel<false><<<gemm_grid, 256>>>(x, We1, be1, dis, xw, h0, N, 128, 128);
    csr_agg_kernel<128><<<AGG_BLOCKS, 256>>>(xw, h0, N);
    gemm_gcn_kernel<false><<<gemm_grid, 256>>>(h0, We2, be2, dis, xw, h1, N, 128, 128);
    csr_agg_kernel<128><<<AGG_BLOCKS, 256>>>(xw, h1, N);
    gemm_gcn_kernel<false><<<gemm_grid, 256>>>(h1, We3, be3, dis, xw, h0, N, 128, 128);
    csr_agg_kernel<128><<<AGG_BLOCKS, 256>>>(xw, h0, N);
    gemm_gcn_kernel<false><<<gemm_grid, 256>>>(h0, We4, be4, dis, xw, h1, N, 128, 128);
    csr_agg_kernel<128><<<AGG_BLOCKS, 256>>>(xw, h1, N);
    head2_sigmoid_kernel<<<(N + 127) / 128, 256>>>(h1, Wt, bt, out + (size_t)N * 16, N);
}

// round 8
// speedup vs baseline: 1.5302x; 1.5302x over previous
#include <cuda_runtime.h>
#include <cuda_bf16.h>
#include <cstdint>
#include <math.h>

#define NNODES 100000
#define NEDGES 1600000
#define MAXF 256
#define SCAN_BS 256

// Scratch (device globals; allocation-free per harness rules)
__device__ float g_dis[NNODES];
__device__ float g_xw[(size_t)NNODES * MAXF];
__device__ float g_h0[(size_t)NNODES * MAXF];
__device__ float g_h1[(size_t)NNODES * MAXF];
__device__ int   g_rows[NEDGES];
__device__ int   g_cols[NEDGES];
__device__ int   g_cnt[NNODES];
__device__ int   g_cur[NNODES];
__device__ int   g_rowptr[NNODES + 1];
__device__ int   g_btot[(NNODES + SCAN_BS - 1) / SCAN_BS + 1];
__device__ int   g_boff[(NNODES + SCAN_BS - 1) / SCAN_BS + 1];
__device__ int   g_csr_src[NEDGES];
__device__ float g_csr_norm[NEDGES];
__device__ int   g_is64;

// ---------------------------------------------------------------------------
// Preprocessing
// ---------------------------------------------------------------------------
__global__ void detect_dtype_kernel(const void* ei_raw, int N) {
    const long long* p = (const long long*)ei_raw;
    int ok = 1;
    for (int i = 0; i < 8; i++) {
        long long v = p[i];
        if (v < 0 || v >= (long long)N) ok = 0;
    }
    g_is64 = ok;
}

__global__ void zero_kernel(int N) {
    int i = blockIdx.x * blockDim.x + threadIdx.x;
    if (i < N) { g_cnt[i] = 0; g_cur[i] = 0; }
}

__global__ void convert_count_kernel(const void* ei_raw, int E) {
    int e = blockIdx.x * blockDim.x + threadIdx.x;
    if (e >= E) return;
    int r, c;
    if (g_is64) {
        const long long* p = (const long long*)ei_raw;
        r = (int)p[e];
        c = (int)p[(size_t)E + e];
    } else {
        const int* p = (const int*)ei_raw;
        r = p[e];
        c = p[E + e];
    }
    g_rows[e] = r;
    g_cols[e] = c;
    atomicAdd(&g_cnt[c], 1);
}

__global__ void scan_blocks_kernel(int N) {
    __shared__ int s[SCAN_BS];
    int i = blockIdx.x * SCAN_BS + threadIdx.x;
    int v = (i < N) ? g_cnt[i] : 0;
    s[threadIdx.x] = v;
    __syncthreads();
    for (int off = 1; off < SCAN_BS; off <<= 1) {
        int t = (threadIdx.x >= off) ? s[threadIdx.x - off] : 0;
        __syncthreads();
        s[threadIdx.x] += t;
        __syncthreads();
    }
    if (i < N) g_rowptr[i] = s[threadIdx.x] - v;
    if (threadIdx.x == SCAN_BS - 1) g_btot[blockIdx.x] = s[SCAN_BS - 1];
}

__global__ void scan_tops_kernel(int nblocks) {
    __shared__ int s[512];
    int v = (threadIdx.x < nblocks) ? g_btot[threadIdx.x] : 0;
    s[threadIdx.x] = v;
    __syncthreads();
    for (int off = 1; off < 512; off <<= 1) {
        int t = (threadIdx.x >= off) ? s[threadIdx.x - off] : 0;
        __syncthreads();
        s[threadIdx.x] += t;
        __syncthreads();
    }
    if (threadIdx.x < nblocks) g_boff[threadIdx.x] = s[threadIdx.x] - v;
}

__global__ void scan_add_kernel(int N, int E) {
    int i = blockIdx.x * SCAN_BS + threadIdx.x;
    if (i < N) g_rowptr[i] += g_boff[blockIdx.x];
    if (i == 0) g_rowptr[N] = E;
}

__global__ void finalize_dis_kernel(int N) {
    int i = blockIdx.x * blockDim.x + threadIdx.x;
    if (i < N) g_dis[i] = rsqrtf((float)g_cnt[i] + 1.0f);
}

__global__ void fill_csr_kernel(int E) {
    int e = blockIdx.x * blockDim.x + threadIdx.x;
    if (e >= E) return;
    int r = g_rows[e];
    int c = g_cols[e];
    int pos = g_rowptr[c] + atomicAdd(&g_cur[c], 1);
    g_csr_src[pos] = r;
    g_csr_norm[pos] = g_dis[r] * g_dis[c];
}

// ---------------------------------------------------------------------------
// mma.sync helpers (baseline PTX, sm_80+, compiles for compute_103)
// ---------------------------------------------------------------------------
__device__ __forceinline__ void mma16816(float* d, const uint32_t* a, const uint32_t* b) {
    asm volatile("mma.sync.aligned.m16n8k16.row.col.f32.bf16.bf16.f32 "
        "{%0,%1,%2,%3}, {%4,%5,%6,%7}, {%8,%9}, {%0,%1,%2,%3};"
        : "+f"(d[0]), "+f"(d[1]), "+f"(d[2]), "+f"(d[3])
        : "r"(a[0]), "r"(a[1]), "r"(a[2]), "r"(a[3]), "r"(b[0]), "r"(b[1]));
}
__device__ __forceinline__ void ldsm4(uint32_t* r, uint32_t addr) {
    asm volatile("ldmatrix.sync.aligned.m8n8.x4.shared.b16 {%0,%1,%2,%3}, [%4];"
        : "=r"(r[0]), "=r"(r[1]), "=r"(r[2]), "=r"(r[3]) : "r"(addr));
}

// ---------------------------------------------------------------------------
// Tensor-core GEMM (bf16 hi/lo 3-pass):
//   D = Ahi*Bhi + Ahi*Blo + Alo*Bhi  (fp32 accumulate)
//   xw = D ; agg = D * dis[row]^2 + bias  (self-loop init)
// CTA tile 128x128, BK=32. 8 warps as 4(m) x 2(n); warp tile 32x64.
// smem padded to 40 bf16 per row (80B stride, conflict-free ldmatrix).
// B stored [n][k]; B fragments via NON-trans ldmatrix (pairs contiguous in k).
// ---------------------------------------------------------------------------
#define BKP 40

template <bool RELU_A>
__global__ __launch_bounds__(256, 2)
void mma_gemm_kernel(const float* __restrict__ A, const float* __restrict__ W,
                     const float* __restrict__ bias, const float* __restrict__ dis,
                     float* __restrict__ xw, float* __restrict__ agg,
                     int N, int K, int F)
{
    __shared__ __nv_bfloat16 sAhi[128 * BKP];
    __shared__ __nv_bfloat16 sAlo[128 * BKP];
    __shared__ __nv_bfloat16 sBhi[128 * BKP];
    __shared__ __nv_bfloat16 sBlo[128 * BKP];

    const int tid = threadIdx.x;
    const int lane = tid & 31;
    const int w = tid >> 5;
    const int wm = w >> 1;          // 0..3
    const int wn = w & 1;           // 0..1
    const int m0 = blockIdx.x * 128;
    const int n0 = blockIdx.y * 128;

    const uint32_t aAhi = (uint32_t)__cvta_generic_to_shared(sAhi);
    const uint32_t aAlo = (uint32_t)__cvta_generic_to_shared(sAlo);
    const uint32_t aBhi = (uint32_t)__cvta_generic_to_shared(sBhi);
    const uint32_t aBlo = (uint32_t)__cvta_generic_to_shared(sBlo);

    // ldmatrix per-lane tile coords
    const int t  = lane >> 3;
    const int tr = lane & 7;
    const int a_row_l = wm * 32 + (t & 1) * 8 + tr;   // + mi*16
    const int a_koff  = (t >> 1) * 8;                 // + kb
    const int b_row_l = wn * 64 + (t >> 1) * 8 + tr;  // + q*16  (n rows)
    const int b_koff  = (t & 1) * 8;                  // + kb    (k offset)

    float acc[2][8][4];
#pragma unroll
    for (int mi = 0; mi < 2; mi++)
#pragma unroll
        for (int nf = 0; nf < 8; nf++)
#pragma unroll
            for (int c = 0; c < 4; c++) acc[mi][nf][c] = 0.f;

    for (int k0 = 0; k0 < K; k0 += 32) {
        // ---- A tile: 128x32 fp32 -> hi/lo bf16 ----
#pragma unroll
        for (int it = 0; it < 4; it++) {
            int i = tid + it * 256;            // 0..1023
            int r = i >> 3;
            int c4 = (i & 7) * 4;
            int row = m0 + r;
            float4 v = make_float4(0.f, 0.f, 0.f, 0.f);
            if (row < N) v = *(const float4*)(A + (size_t)row * K + k0 + c4);
            if (RELU_A) {
                v.x = fmaxf(v.x, 0.f); v.y = fmaxf(v.y, 0.f);
                v.z = fmaxf(v.z, 0.f); v.w = fmaxf(v.w, 0.f);
            }
            __nv_bfloat16 h0 = __float2bfloat16(v.x), h1 = __float2bfloat16(v.y);
            __nv_bfloat16 h2 = __float2bfloat16(v.z), h3 = __float2bfloat16(v.w);
            __nv_bfloat16 l0 = __float2bfloat16(v.x - __bfloat162float(h0));
            __nv_bfloat16 l1 = __float2bfloat16(v.y - __bfloat162float(h1));
            __nv_bfloat16 l2 = __float2bfloat16(v.z - __bfloat162float(h2));
            __nv_bfloat16 l3 = __float2bfloat16(v.w - __bfloat162float(h3));
            uint2 ph, pl;
            __nv_bfloat162 tt;
            tt = __nv_bfloat162(h0, h1); ph.x = *(uint32_t*)&tt;
            tt = __nv_bfloat162(h2, h3); ph.y = *(uint32_t*)&tt;
            tt = __nv_bfloat162(l0, l1); pl.x = *(uint32_t*)&tt;
            tt = __nv_bfloat162(l2, l3); pl.y = *(uint32_t*)&tt;
            *(uint2*)&sAhi[r * BKP + c4] = ph;
            *(uint2*)&sAlo[r * BKP + c4] = pl;
        }

        // ---- B tile: W[k0..k0+32][n0..n0+128] -> [n][k] hi/lo ----
#pragma unroll
        for (int it = 0; it < 16; it++) {
            int i = tid + it * 256;            // 0..4095
            int kr = i >> 7;
            int n = i & 127;
            float wv = W[(size_t)(k0 + kr) * F + n0 + n];
            __nv_bfloat16 h = __float2bfloat16(wv);
            __nv_bfloat16 l = __float2bfloat16(wv - __bfloat162float(h));
            sBhi[n * BKP + kr] = h;
            sBlo[n * BKP + kr] = l;
        }
        __syncthreads();

        // ---- 2 k16-steps ----
#pragma unroll
        for (int s = 0; s < 2; s++) {
            const int kb = s * 16;
            uint32_t ahi[2][4], alo[2][4];
#pragma unroll
            for (int mi = 0; mi < 2; mi++) {
                uint32_t off = (uint32_t)(((a_row_l + mi * 16) * BKP + kb + a_koff) * 2);
                ldsm4(ahi[mi], aAhi + off);
                ldsm4(alo[mi], aAlo + off);
            }
            uint32_t bhi[8][2], blo[8][2];
#pragma unroll
            for (int q = 0; q < 4; q++) {
                uint32_t off = (uint32_t)(((b_row_l + q * 16) * BKP + kb + b_koff) * 2);
                uint32_t r4[4];
                ldsm4(r4, aBhi + off);
                bhi[2 * q][0] = r4[0]; bhi[2 * q][1] = r4[1];
                bhi[2 * q + 1][0] = r4[2]; bhi[2 * q + 1][1] = r4[3];
                ldsm4(r4, aBlo + off);
                blo[2 * q][0] = r4[0]; blo[2 * q][1] = r4[1];
                blo[2 * q + 1][0] = r4[2]; blo[2 * q + 1][1] = r4[3];
            }
#pragma unroll
            for (int mi = 0; mi < 2; mi++)
#pragma unroll
                for (int nf = 0; nf < 8; nf++) {
                    mma16816(acc[mi][nf], ahi[mi], bhi[nf]);
                    mma16816(acc[mi][nf], ahi[mi], blo[nf]);
                    mma16816(acc[mi][nf], alo[mi], bhi[nf]);
                }
        }
        __syncthreads();
    }

    // ---- epilogue: write xw and agg (self-loop init) ----
    const int crow0 = m0 + wm * 32 + (lane >> 2);
    const int ccol0 = n0 + wn * 64 + (lane & 3) * 2;
#pragma unroll
    for (int mi = 0; mi < 2; mi++) {
        int r1 = crow0 + mi * 16;
        int r2 = r1 + 8;
        float d1 = 0.f, d2v = 0.f;
        if (r1 < N) { float d = dis[r1]; d1 = d * d; }
        if (r2 < N) { float d = dis[r2]; d2v = d * d; }
#pragma unroll
        for (int nf = 0; nf < 8; nf++) {
            int col = ccol0 + nf * 8;
            float b0 = bias[col], b1 = bias[col + 1];
            if (r1 < N) {
                size_t o = (size_t)r1 * F + col;
                float2 v = make_float2(acc[mi][nf][0], acc[mi][nf][1]);
                *(float2*)(xw + o) = v;
                *(float2*)(agg + o) = make_float2(v.x * d1 + b0, v.y * d1 + b1);
            }
            if (r2 < N) {
                size_t o = (size_t)r2 * F + col;
                float2 v = make_float2(acc[mi][nf][2], acc[mi][nf][3]);
                *(float2*)(xw + o) = v;
                *(float2*)(agg + o) = make_float2(v.x * d2v + b0, v.y * d2v + b1);
            }
        }
    }
}

// ---------------------------------------------------------------------------
// CSR gather-side aggregation (no atomics)
// ---------------------------------------------------------------------------
template <int F>
__global__ __launch_bounds__(256)
void csr_agg_kernel(const float* __restrict__ xw, float* __restrict__ agg, int N)
{
    const int lane = threadIdx.x & 31;
    const int node = (blockIdx.x * blockDim.x + threadIdx.x) >> 5;
    if (node >= N) return;

    int beg = g_rowptr[node];
    int end = g_rowptr[node + 1];
    if (beg == end) return;

    constexpr int NV = F / 128;
    float4 acc[NV];
#pragma unroll
    for (int q = 0; q < NV; q++) acc[q] = make_float4(0.f, 0.f, 0.f, 0.f);

    for (int base = beg; base < end; base += 32) {
        int n = min(32, end - base);
        int srcReg = 0; float nrReg = 0.f;
        if (lane < n) {
            srcReg = g_csr_src[base + lane];
            nrReg  = g_csr_norm[base + lane];
        }
        for (int k = 0; k < n; k++) {
            int   r = __shfl_sync(0xffffffffu, srcReg, k);
            float w = __shfl_sync(0xffffffffu, nrReg, k);
            const float4* s = (const float4*)(xw + (size_t)r * F);
#pragma unroll
            for (int q = 0; q < NV; q++) {
                float4 v = s[lane + q * 32];
                acc[q].x += w * v.x;
                acc[q].y += w * v.y;
                acc[q].z += w * v.z;
                acc[q].w += w * v.w;
            }
        }
    }

    float4* d = (float4*)(agg + (size_t)node * F);
#pragma unroll
    for (int q = 0; q < NV; q++) {
        float4 cur = d[lane + q * 32];
        cur.x += acc[q].x; cur.y += acc[q].y;
        cur.z += acc[q].z; cur.w += acc[q].w;
        d[lane + q * 32] = cur;
    }
}

// ---------------------------------------------------------------------------
// Heads
// ---------------------------------------------------------------------------
__global__ __launch_bounds__(256)
void head16_kernel(const float* __restrict__ A, const float* __restrict__ Wc,
                   const float* __restrict__ bc, float* __restrict__ out, int N)
{
    __shared__ float Ws[128 * 16];
    __shared__ float bs[16];
    for (int i = threadIdx.x; i < 128 * 16; i += 256) Ws[i] = Wc[i];
    if (threadIdx.x < 16) bs[threadIdx.x] = bc[threadIdx.x];
    __syncthreads();

    int j = threadIdx.x & 15;
    int rl = threadIdx.x >> 4;
    int row = blockIdx.x * 16 + rl;
    if (row >= N) return;

    const float* a = A + (size_t)row * 128;
    float acc = 0.f;
#pragma unroll 8
    for (int k = 0; k < 128; k++) acc += a[k] * Ws[k * 16 + j];
    out[(size_t)row * 16 + j] = acc + bs[j];
}

__global__ __launch_bounds__(256)
void head2_sigmoid_kernel(const float* __restrict__ A, const float* __restrict__ Wt,
                          const float* __restrict__ bt, float* __restrict__ out, int N)
{
    __shared__ float Ws[128 * 2];
    __shared__ float bs[2];
    for (int i = threadIdx.x; i < 128 * 2; i += 256) Ws[i] = Wt[i];
    if (threadIdx.x < 2) bs[threadIdx.x] = bt[threadIdx.x];
    __syncthreads();

    int j = threadIdx.x & 1;
    int rl = threadIdx.x >> 1;
    int row = blockIdx.x * 128 + rl;
    if (row >= N) return;

    const float* a = A + (size_t)row * 128;
    float acc = 0.f;
#pragma unroll 8
    for (int k = 0; k < 128; k++) acc += a[k] * Ws[k * 2 + j];
    float z = acc + bs[j];
    out[(size_t)row * 2 + j] = 1.0f / (1.0f + expf(-z));
}

// ---------------------------------------------------------------------------
// Launch
// ---------------------------------------------------------------------------
extern "C" void kernel_launch(void* const* d_in, const int* in_sizes, int n_in,
                              void* d_out, int out_size)
{
    const float* x = (const float*)d_in[0];
    const void* ei = d_in[1];
    const float* W1  = (const float*)d_in[2];
    const float* b1  = (const float*)d_in[3];
    const float* W2  = (const float*)d_in[4];
    const float* b2  = (const float*)d_in[5];
    const float* Wc  = (const float*)d_in[6];
    const float* bc  = (const float*)d_in[7];
    const float* We1 = (const float*)d_in[8];
    const float* be1 = (const float*)d_in[9];
    const float* We2 = (const float*)d_in[10];
    const float* be2 = (const float*)d_in[11];
    const float* We3 = (const float*)d_in[12];
    const float* be3 = (const float*)d_in[13];
    const float* We4 = (const float*)d_in[14];
    const float* be4 = (const float*)d_in[15];
    const float* Wt  = (const float*)d_in[16];
    const float* bt  = (const float*)d_in[17];
    float* out = (float*)d_out;

    const int N = in_sizes[0] / 128;
    const int E = in_sizes[1] / 2;
    const int nscan = (N + SCAN_BS - 1) / SCAN_BS;

    float *dis, *xw, *h0, *h1;
    cudaGetSymbolAddress((void**)&dis, g_dis);
    cudaGetSymbolAddress((void**)&xw, g_xw);
    cudaGetSymbolAddress((void**)&h0, g_h0);
    cudaGetSymbolAddress((void**)&h1, g_h1);

    // --- preprocessing: dtype, degrees, scan, CSR, norms ---
    detect_dtype_kernel<<<1, 1>>>(ei, N);
    zero_kernel<<<(N + 255) / 256, 256>>>(N);
    convert_count_kernel<<<(E + 255) / 256, 256>>>(ei, E);
    scan_blocks_kernel<<<nscan, SCAN_BS>>>(N);
    scan_tops_kernel<<<1, 512>>>(nscan);
    scan_add_kernel<<<nscan, SCAN_BS>>>(N, E);
    finalize_dis_kernel<<<(N + 255) / 256, 256>>>(N);
    fill_csr_kernel<<<(E + 255) / 256, 256>>>(E);

    dim3 gw((N + 127) / 128, 2);   // F=256
    dim3 g1((N + 127) / 128, 1);   // F=128
    const int AGG_BLOCKS = (N + 7) / 8;

    // --- classification branch ---
    mma_gemm_kernel<false><<<gw, 256>>>(x, W1, b1, dis, xw, h0, N, 128, 256);
    csr_agg_kernel<256><<<AGG_BLOCKS, 256>>>(xw, h0, N);
    mma_gemm_kernel<true><<<g1, 256>>>(h0, W2, b2, dis, xw, h1, N, 256, 128);
    csr_agg_kernel<128><<<AGG_BLOCKS, 256>>>(xw, h1, N);
    head16_kernel<<<(N + 15) / 16, 256>>>(h1, Wc, bc, out, N);

    // --- encoder branch ---
    mma_gemm_kernel<false><<<g1, 256>>>(x, We1, be1, dis, xw, h0, N, 128, 128);
    csr_agg_kernel<128><<<AGG_BLOCKS, 256>>>(xw, h0, N);
    mma_gemm_kernel<false><<<g1, 256>>>(h0, We2, be2, dis, xw, h1, N, 128, 128);
    csr_agg_kernel<128><<<AGG_BLOCKS, 256>>>(xw, h1, N);
    mma_gemm_kernel<false><<<g1, 256>>>(h1, We3, be3, dis, xw, h0, N, 128, 128);
    csr_agg_kernel<128><<<AGG_BLOCKS, 256>>>(xw, h0, N);
    mma_gemm_kernel<false><<<g1, 256>>>(h0, We4, be4, dis, xw, h1, N, 128, 128);
    csr_agg_kernel<128><<<AGG_BLOCKS, 256>>>(xw, h1, N);
    head2_sigmoid_kernel<<<(N + 127) / 128, 256>>>(h1, Wt, bt, out + (size_t)N * 16, N);
}

// round 9
// speedup vs baseline: 1.8904x; 1.2354x over previous
#include <cuda_runtime.h>
#include <cuda_bf16.h>
#include <cstdint>
#include <math.h>

#define NNODES 100000
#define NEDGES 1600000
#define MAXF 256
#define SCAN_BS 256

// Scratch (device globals; allocation-free per harness rules)
__device__ float g_dis[NNODES];
__device__ float g_xw[(size_t)NNODES * MAXF];
__device__ float g_h0[(size_t)NNODES * MAXF];
__device__ float g_h1[(size_t)NNODES * MAXF];
__device__ float g_aggx[(size_t)NNODES * 128];
__device__ int   g_rows[NEDGES];
__device__ int   g_cols[NEDGES];
__device__ int   g_cnt[NNODES];
__device__ int   g_cur[NNODES];
__device__ int   g_rowptr[NNODES + 1];
__device__ int   g_btot[(NNODES + SCAN_BS - 1) / SCAN_BS + 1];
__device__ int   g_boff[(NNODES + SCAN_BS - 1) / SCAN_BS + 1];
__device__ int   g_csr_src[NEDGES];
__device__ float g_csr_norm[NEDGES];
__device__ int   g_is64;
// pre-converted weights, [n][k] layout, bf16 hi/lo. 131072 elems total.
__device__ __nv_bfloat16 g_whi[131072];
__device__ __nv_bfloat16 g_wlo[131072];

// ---------------------------------------------------------------------------
// Preprocessing
// ---------------------------------------------------------------------------
__global__ void detect_dtype_kernel(const void* ei_raw, int N) {
    const long long* p = (const long long*)ei_raw;
    int ok = 1;
    for (int i = 0; i < 8; i++) {
        long long v = p[i];
        if (v < 0 || v >= (long long)N) ok = 0;
    }
    g_is64 = ok;
}

__global__ void zero_kernel(int N) {
    int i = blockIdx.x * blockDim.x + threadIdx.x;
    if (i < N) { g_cnt[i] = 0; g_cur[i] = 0; }
}

__global__ void convert_count_kernel(const void* ei_raw, int E) {
    int e = blockIdx.x * blockDim.x + threadIdx.x;
    if (e >= E) return;
    int r, c;
    if (g_is64) {
        const long long* p = (const long long*)ei_raw;
        r = (int)p[e];
        c = (int)p[(size_t)E + e];
    } else {
        const int* p = (const int*)ei_raw;
        r = p[e];
        c = p[E + e];
    }
    g_rows[e] = r;
    g_cols[e] = c;
    atomicAdd(&g_cnt[c], 1);
}

__global__ void scan_blocks_kernel(int N) {
    __shared__ int s[SCAN_BS];
    int i = blockIdx.x * SCAN_BS + threadIdx.x;
    int v = (i < N) ? g_cnt[i] : 0;
    s[threadIdx.x] = v;
    __syncthreads();
    for (int off = 1; off < SCAN_BS; off <<= 1) {
        int t = (threadIdx.x >= off) ? s[threadIdx.x - off] : 0;
        __syncthreads();
        s[threadIdx.x] += t;
        __syncthreads();
    }
    if (i < N) g_rowptr[i] = s[threadIdx.x] - v;
    if (threadIdx.x == SCAN_BS - 1) g_btot[blockIdx.x] = s[SCAN_BS - 1];
}

__global__ void scan_tops_kernel(int nblocks) {
    __shared__ int s[512];
    int v = (threadIdx.x < nblocks) ? g_btot[threadIdx.x] : 0;
    s[threadIdx.x] = v;
    __syncthreads();
    for (int off = 1; off < 512; off <<= 1) {
        int t = (threadIdx.x >= off) ? s[threadIdx.x - off] : 0;
        __syncthreads();
        s[threadIdx.x] += t;
        __syncthreads();
    }
    if (threadIdx.x < nblocks) g_boff[threadIdx.x] = s[threadIdx.x] - v;
}

__global__ void scan_add_kernel(int N, int E) {
    int i = blockIdx.x * SCAN_BS + threadIdx.x;
    if (i < N) g_rowptr[i] += g_boff[blockIdx.x];
    if (i == 0) g_rowptr[N] = E;
}

__global__ void finalize_dis_kernel(int N) {
    int i = blockIdx.x * blockDim.x + threadIdx.x;
    if (i < N) g_dis[i] = rsqrtf((float)g_cnt[i] + 1.0f);
}

__global__ void fill_csr_kernel(int E) {
    int e = blockIdx.x * blockDim.x + threadIdx.x;
    if (e >= E) return;
    int r = g_rows[e];
    int c = g_cols[e];
    int pos = g_rowptr[c] + atomicAdd(&g_cur[c], 1);
    g_csr_src[pos] = r;
    g_csr_norm[pos] = g_dis[r] * g_dis[c];
}

// Weight pre-conversion: W [K][F] fp32 -> whi/wlo [F][K] bf16 at given offset
__global__ void conv_w_kernel(const float* __restrict__ W, int K, int F, int off) {
    int idx = blockIdx.x * blockDim.x + threadIdx.x;
    if (idx >= K * F) return;
    int k = idx / F;
    int n = idx % F;
    float wv = W[idx];
    __nv_bfloat16 h = __float2bfloat16(wv);
    g_whi[off + n * K + k] = h;
    g_wlo[off + n * K + k] = __float2bfloat16(wv - __bfloat162float(h));
}

// ---------------------------------------------------------------------------
// mma.sync helpers (baseline PTX, sm_80+, compiles for compute_103)
// ---------------------------------------------------------------------------
__device__ __forceinline__ void mma16816(float* d, const uint32_t* a, const uint32_t* b) {
    asm volatile("mma.sync.aligned.m16n8k16.row.col.f32.bf16.bf16.f32 "
        "{%0,%1,%2,%3}, {%4,%5,%6,%7}, {%8,%9}, {%0,%1,%2,%3};"
        : "+f"(d[0]), "+f"(d[1]), "+f"(d[2]), "+f"(d[3])
        : "r"(a[0]), "r"(a[1]), "r"(a[2]), "r"(a[3]), "r"(b[0]), "r"(b[1]));
}
__device__ __forceinline__ void ldsm4(uint32_t* r, uint32_t addr) {
    asm volatile("ldmatrix.sync.aligned.m8n8.x4.shared.b16 {%0,%1,%2,%3}, [%4];"
        : "=r"(r[0]), "=r"(r[1]), "=r"(r[2]), "=r"(r[3]) : "r"(addr));
}

// ---------------------------------------------------------------------------
// Tensor-core GEMM (bf16 hi/lo 3-pass):  D = Ahi*Bhi + Ahi*Blo + Alo*Bhi
// DUAL:  xw = D ; agg = D * dis[row]^2 + bias    (self-loop init for csr_agg)
// !DUAL: out = D + bias                          (plain; A already propagated)
// CTA tile 128x128, BK=32. 8 warps 4(m)x2(n). B pre-converted [n][k] global.
// ---------------------------------------------------------------------------
#define BKP 40

template <bool RELU_A, bool DUAL>
__global__ __launch_bounds__(256, 2)
void mma_gemm_kernel(const float* __restrict__ A,
                     const __nv_bfloat16* __restrict__ whi,
                     const __nv_bfloat16* __restrict__ wlo,
                     const float* __restrict__ bias, const float* __restrict__ dis,
                     float* __restrict__ xw, float* __restrict__ agg,
                     int N, int K, int F)
{
    __shared__ __nv_bfloat16 sAhi[128 * BKP];
    __shared__ __nv_bfloat16 sAlo[128 * BKP];
    __shared__ __nv_bfloat16 sBhi[128 * BKP];
    __shared__ __nv_bfloat16 sBlo[128 * BKP];

    const int tid = threadIdx.x;
    const int lane = tid & 31;
    const int w = tid >> 5;
    const int wm = w >> 1;
    const int wn = w & 1;
    const int m0 = blockIdx.x * 128;
    const int n0 = blockIdx.y * 128;

    const uint32_t aAhi = (uint32_t)__cvta_generic_to_shared(sAhi);
    const uint32_t aAlo = (uint32_t)__cvta_generic_to_shared(sAlo);
    const uint32_t aBhi = (uint32_t)__cvta_generic_to_shared(sBhi);
    const uint32_t aBlo = (uint32_t)__cvta_generic_to_shared(sBlo);

    const int t  = lane >> 3;
    const int tr = lane & 7;
    const int a_row_l = wm * 32 + (t & 1) * 8 + tr;
    const int a_koff  = (t >> 1) * 8;
    const int b_row_l = wn * 64 + (t >> 1) * 8 + tr;
    const int b_koff  = (t & 1) * 8;

    float acc[2][8][4];
#pragma unroll
    for (int mi = 0; mi < 2; mi++)
#pragma unroll
        for (int nf = 0; nf < 8; nf++)
#pragma unroll
            for (int c = 0; c < 4; c++) acc[mi][nf][c] = 0.f;

    for (int k0 = 0; k0 < K; k0 += 32) {
        // ---- A tile: 128x32 fp32 -> hi/lo bf16 ----
#pragma unroll
        for (int it = 0; it < 4; it++) {
            int i = tid + it * 256;
            int r = i >> 3;
            int c4 = (i & 7) * 4;
            int row = m0 + r;
            float4 v = make_float4(0.f, 0.f, 0.f, 0.f);
            if (row < N) v = *(const float4*)(A + (size_t)row * K + k0 + c4);
            if (RELU_A) {
                v.x = fmaxf(v.x, 0.f); v.y = fmaxf(v.y, 0.f);
                v.z = fmaxf(v.z, 0.f); v.w = fmaxf(v.w, 0.f);
            }
            __nv_bfloat16 h0 = __float2bfloat16(v.x), h1 = __float2bfloat16(v.y);
            __nv_bfloat16 h2 = __float2bfloat16(v.z), h3 = __float2bfloat16(v.w);
            __nv_bfloat16 l0 = __float2bfloat16(v.x - __bfloat162float(h0));
            __nv_bfloat16 l1 = __float2bfloat16(v.y - __bfloat162float(h1));
            __nv_bfloat16 l2 = __float2bfloat16(v.z - __bfloat162float(h2));
            __nv_bfloat16 l3 = __float2bfloat16(v.w - __bfloat162float(h3));
            uint2 ph, pl;
            __nv_bfloat162 tt;
            tt = __nv_bfloat162(h0, h1); ph.x = *(uint32_t*)&tt;
            tt = __nv_bfloat162(h2, h3); ph.y = *(uint32_t*)&tt;
            tt = __nv_bfloat162(l0, l1); pl.x = *(uint32_t*)&tt;
            tt = __nv_bfloat162(l2, l3); pl.y = *(uint32_t*)&tt;
            *(uint2*)&sAhi[r * BKP + c4] = ph;
            *(uint2*)&sAlo[r * BKP + c4] = pl;
        }

        // ---- B tile: pre-converted [n][k] bf16, vectorized copy ----
#pragma unroll
        for (int it = 0; it < 2; it++) {
            int i = tid + it * 256;          // 0..511
            int n = i >> 2;
            int k8 = (i & 3) * 8;
            size_t go = (size_t)(n0 + n) * K + k0 + k8;
            *(uint4*)&sBhi[n * BKP + k8] = *(const uint4*)(whi + go);
            *(uint4*)&sBlo[n * BKP + k8] = *(const uint4*)(wlo + go);
        }
        __syncthreads();

        // ---- 2 k16-steps ----
#pragma unroll
        for (int s = 0; s < 2; s++) {
            const int kb = s * 16;
            uint32_t ahi[2][4], alo[2][4];
#pragma unroll
            for (int mi = 0; mi < 2; mi++) {
                uint32_t off = (uint32_t)(((a_row_l + mi * 16) * BKP + kb + a_koff) * 2);
                ldsm4(ahi[mi], aAhi + off);
                ldsm4(alo[mi], aAlo + off);
            }
            uint32_t bhi[8][2], blo[8][2];
#pragma unroll
            for (int q = 0; q < 4; q++) {
                uint32_t off = (uint32_t)(((b_row_l + q * 16) * BKP + kb + b_koff) * 2);
                uint32_t r4[4];
                ldsm4(r4, aBhi + off);
                bhi[2 * q][0] = r4[0]; bhi[2 * q][1] = r4[1];
                bhi[2 * q + 1][0] = r4[2]; bhi[2 * q + 1][1] = r4[3];
                ldsm4(r4, aBlo + off);
                blo[2 * q][0] = r4[0]; blo[2 * q][1] = r4[1];
                blo[2 * q + 1][0] = r4[2]; blo[2 * q + 1][1] = r4[3];
            }
#pragma unroll
            for (int mi = 0; mi < 2; mi++)
#pragma unroll
                for (int nf = 0; nf < 8; nf++) {
                    mma16816(acc[mi][nf], ahi[mi], bhi[nf]);
                    mma16816(acc[mi][nf], ahi[mi], blo[nf]);
                    mma16816(acc[mi][nf], alo[mi], bhi[nf]);
                }
        }
        __syncthreads();
    }

    // ---- epilogue ----
    const int crow0 = m0 + wm * 32 + (lane >> 2);
    const int ccol0 = n0 + wn * 64 + (lane & 3) * 2;
#pragma unroll
    for (int mi = 0; mi < 2; mi++) {
        int r1 = crow0 + mi * 16;
        int r2 = r1 + 8;
        float d1 = 0.f, d2v = 0.f;
        if (DUAL) {
            if (r1 < N) { float d = dis[r1]; d1 = d * d; }
            if (r2 < N) { float d = dis[r2]; d2v = d * d; }
        }
#pragma unroll
        for (int nf = 0; nf < 8; nf++) {
            int col = ccol0 + nf * 8;
            float b0 = bias[col], b1 = bias[col + 1];
            if (r1 < N) {
                size_t o = (size_t)r1 * F + col;
                float2 v = make_float2(acc[mi][nf][0], acc[mi][nf][1]);
                if (DUAL) {
                    *(float2*)(xw + o) = v;
                    *(float2*)(agg + o) = make_float2(v.x * d1 + b0, v.y * d1 + b1);
                } else {
                    *(float2*)(agg + o) = make_float2(v.x + b0, v.y + b1);
                }
            }
            if (r2 < N) {
                size_t o = (size_t)r2 * F + col;
                float2 v = make_float2(acc[mi][nf][2], acc[mi][nf][3]);
                if (DUAL) {
                    *(float2*)(xw + o) = v;
                    *(float2*)(agg + o) = make_float2(v.x * d2v + b0, v.y * d2v + b1);
                } else {
                    *(float2*)(agg + o) = make_float2(v.x + b0, v.y + b1);
                }
            }
        }
    }
}

// ---------------------------------------------------------------------------
// CSR gather-side aggregation (no atomics)
// INIT: out = sum + dis[node]^2 * src_feat[node]   (fresh propagation of x)
// !INIT: agg[node] += sum                          (read-modify, self term done)
// ---------------------------------------------------------------------------
template <int F, bool INIT>
__global__ __launch_bounds__(256)
void csr_agg_kernel(const float* __restrict__ xw, float* __restrict__ agg,
                    const float* __restrict__ dis, int N)
{
    const int lane = threadIdx.x & 31;
    const int node = (blockIdx.x * blockDim.x + threadIdx.x) >> 5;
    if (node >= N) return;

    int beg = g_rowptr[node];
    int end = g_rowptr[node + 1];
    if (!INIT && beg == end) return;

    constexpr int NV = F / 128;
    float4 acc[NV];
#pragma unroll
    for (int q = 0; q < NV; q++) acc[q] = make_float4(0.f, 0.f, 0.f, 0.f);

    for (int base = beg; base < end; base += 32) {
        int n = min(32, end - base);
        int srcReg = 0; float nrReg = 0.f;
        if (lane < n) {
            srcReg = g_csr_src[base + lane];
            nrReg  = g_csr_norm[base + lane];
        }
        for (int k = 0; k < n; k++) {
            int   r = __shfl_sync(0xffffffffu, srcReg, k);
            float w = __shfl_sync(0xffffffffu, nrReg, k);
            const float4* s = (const float4*)(xw + (size_t)r * F);
#pragma unroll
            for (int q = 0; q < NV; q++) {
                float4 v = s[lane + q * 32];
                acc[q].x += w * v.x;
                acc[q].y += w * v.y;
                acc[q].z += w * v.z;
                acc[q].w += w * v.w;
            }
        }
    }

    float4* d = (float4*)(agg + (size_t)node * F);
    if (INIT) {
        float dd = dis[node];
        float d2 = dd * dd;
        const float4* sx = (const float4*)(xw + (size_t)node * F);
#pragma unroll
        for (int q = 0; q < NV; q++) {
            float4 sv = sx[lane + q * 32];
            d[lane + q * 32] = make_float4(acc[q].x + d2 * sv.x,
                                           acc[q].y + d2 * sv.y,
                                           acc[q].z + d2 * sv.z,
                                           acc[q].w + d2 * sv.w);
        }
    } else {
#pragma unroll
        for (int q = 0; q < NV; q++) {
            float4 cur = d[lane + q * 32];
            cur.x += acc[q].x; cur.y += acc[q].y;
            cur.z += acc[q].z; cur.w += acc[q].w;
            d[lane + q * 32] = cur;
        }
    }
}

// ---------------------------------------------------------------------------
// Heads
// ---------------------------------------------------------------------------
__global__ __launch_bounds__(256)
void head16_kernel(const float* __restrict__ A, const float* __restrict__ Wc,
                   const float* __restrict__ bc, float* __restrict__ out, int N)
{
    __shared__ float Ws[128 * 16];
    __shared__ float bs[16];
    for (int i = threadIdx.x; i < 128 * 16; i += 256) Ws[i] = Wc[i];
    if (threadIdx.x < 16) bs[threadIdx.x] = bc[threadIdx.x];
    __syncthreads();

    int j = threadIdx.x & 15;
    int rl = threadIdx.x >> 4;
    int row = blockIdx.x * 16 + rl;
    if (row >= N) return;

    const float* a = A + (size_t)row * 128;
    float acc = 0.f;
#pragma unroll 8
    for (int k = 0; k < 128; k++) acc += a[k] * Ws[k * 16 + j];
    out[(size_t)row * 16 + j] = acc + bs[j];
}

__global__ __launch_bounds__(256)
void head2_sigmoid_kernel(const float* __restrict__ A, const float* __restrict__ Wt,
                          const float* __restrict__ bt, float* __restrict__ out, int N)
{
    __shared__ float Ws[128 * 2];
    __shared__ float bs[2];
    for (int i = threadIdx.x; i < 128 * 2; i += 256) Ws[i] = Wt[i];
    if (threadIdx.x < 2) bs[threadIdx.x] = bt[threadIdx.x];
    __syncthreads();

    int j = threadIdx.x & 1;
    int rl = threadIdx.x >> 1;
    int row = blockIdx.x * 128 + rl;
    if (row >= N) return;

    const float* a = A + (size_t)row * 128;
    float acc = 0.f;
#pragma unroll 8
    for (int k = 0; k < 128; k++) acc += a[k] * Ws[k * 2 + j];
    float z = acc + bs[j];
    out[(size_t)row * 2 + j] = 1.0f / (1.0f + expf(-z));
}

// ---------------------------------------------------------------------------
// Launch
// ---------------------------------------------------------------------------
extern "C" void kernel_launch(void* const* d_in, const int* in_sizes, int n_in,
                              void* d_out, int out_size)
{
    const float* x = (const float*)d_in[0];
    const void* ei = d_in[1];
    const float* W1  = (const float*)d_in[2];
    const float* b1  = (const float*)d_in[3];
    const float* W2  = (const float*)d_in[4];
    const float* b2  = (const float*)d_in[5];
    const float* Wc  = (const float*)d_in[6];
    const float* bc  = (const float*)d_in[7];
    const float* We1 = (const float*)d_in[8];
    const float* be1 = (const float*)d_in[9];
    const float* We2 = (const float*)d_in[10];
    const float* be2 = (const float*)d_in[11];
    const float* We3 = (const float*)d_in[12];
    const float* be3 = (const float*)d_in[13];
    const float* We4 = (const float*)d_in[14];
    const float* be4 = (const float*)d_in[15];
    const float* Wt  = (const float*)d_in[16];
    const float* bt  = (const float*)d_in[17];
    float* out = (float*)d_out;

    const int N = in_sizes[0] / 128;
    const int E = in_sizes[1] / 2;
    const int nscan = (N + SCAN_BS - 1) / SCAN_BS;

    float *dis, *xw, *h0, *h1, *aggx;
    __nv_bfloat16 *whi, *wlo;
    cudaGetSymbolAddress((void**)&dis, g_dis);
    cudaGetSymbolAddress((void**)&xw, g_xw);
    cudaGetSymbolAddress((void**)&h0, g_h0);
    cudaGetSymbolAddress((void**)&h1, g_h1);
    cudaGetSymbolAddress((void**)&aggx, g_aggx);
    cudaGetSymbolAddress((void**)&whi, g_whi);
    cudaGetSymbolAddress((void**)&wlo, g_wlo);

    // weight offsets in g_whi/g_wlo: [n][k] per layer
    const int OFF_W1 = 0;        // K=128,F=256 -> 32768
    const int OFF_W2 = 32768;    // K=256,F=128 -> 32768
    const int OFF_E1 = 65536;    // 128x128
    const int OFF_E2 = 81920;
    const int OFF_E3 = 98304;
    const int OFF_E4 = 114688;

    // --- preprocessing: dtype, degrees, scan, CSR, norms, weights ---
    detect_dtype_kernel<<<1, 1>>>(ei, N);
    zero_kernel<<<(N + 255) / 256, 256>>>(N);
    convert_count_kernel<<<(E + 255) / 256, 256>>>(ei, E);
    scan_blocks_kernel<<<nscan, SCAN_BS>>>(N);
    scan_tops_kernel<<<1, 512>>>(nscan);
    scan_add_kernel<<<nscan, SCAN_BS>>>(N, E);
    finalize_dis_kernel<<<(N + 255) / 256, 256>>>(N);
    fill_csr_kernel<<<(E + 255) / 256, 256>>>(E);
    conv_w_kernel<<<128, 256>>>(W1, 128, 256, OFF_W1);
    conv_w_kernel<<<128, 256>>>(W2, 256, 128, OFF_W2);
    conv_w_kernel<<<64, 256>>>(We1, 128, 128, OFF_E1);
    conv_w_kernel<<<64, 256>>>(We2, 128, 128, OFF_E2);
    conv_w_kernel<<<64, 256>>>(We3, 128, 128, OFF_E3);
    conv_w_kernel<<<64, 256>>>(We4, 128, 128, OFF_E4);

    dim3 gw((N + 127) / 128, 2);   // F=256
    dim3 g1((N + 127) / 128, 1);   // F=128
    const int AGG_BLOCKS = (N + 7) / 8;

    // --- shared propagated input: aggx = D^-1/2 (A+I) D^-1/2 x ---
    csr_agg_kernel<128, true><<<AGG_BLOCKS, 256>>>(x, aggx, dis, N);

    // --- classification branch ---
    // h0 = aggx @ W1 + b1   (plain; relu applied at next layer's A-load)
    mma_gemm_kernel<false, false><<<gw, 256>>>(aggx, whi + OFF_W1, wlo + OFF_W1,
                                               b1, dis, nullptr, h0, N, 128, 256);
    // xw = relu(h0) @ W2 ; h1 = xw*dis^2 + b2 ; h1 += edges
    mma_gemm_kernel<true, true><<<g1, 256>>>(h0, whi + OFF_W2, wlo + OFF_W2,
                                             b2, dis, xw, h1, N, 256, 128);
    csr_agg_kernel<128, false><<<AGG_BLOCKS, 256>>>(xw, h1, dis, N);
    head16_kernel<<<(N + 15) / 16, 256>>>(h1, Wc, bc, out, N);

    // --- encoder branch ---
    // he1 = aggx @ We1 + be1 (plain, reuses aggx)
    mma_gemm_kernel<false, false><<<g1, 256>>>(aggx, whi + OFF_E1, wlo + OFF_E1,
                                               be1, dis, nullptr, h0, N, 128, 128);
    mma_gemm_kernel<false, true><<<g1, 256>>>(h0, whi + OFF_E2, wlo + OFF_E2,
                                              be2, dis, xw, h1, N, 128, 128);
    csr_agg_kernel<128, false><<<AGG_BLOCKS, 256>>>(xw, h1, dis, N);
    mma_gemm_kernel<false, true><<<g1, 256>>>(h1, whi + OFF_E3, wlo + OFF_E3,
                                              be3, dis, xw, h0, N, 128, 128);
    csr_agg_kernel<128, false><<<AGG_BLOCKS, 256>>>(xw, h0, dis, N);
    mma_gemm_kernel<false, true><<<g1, 256>>>(h0, whi + OFF_E4, wlo + OFF_E4,
                                              be4, dis, xw, h1, N, 128, 128);
    csr_agg_kernel<128, false><<<AGG_BLOCKS, 256>>>(xw, h1, dis, N);
    head2_sigmoid_kernel<<<(N + 127) / 128, 256>>>(h1, Wt, bt, out + (size_t)N * 16, N);
}